// round 11
// baseline (speedup 1.0000x reference)
#include <cuda_runtime.h>
#include <cstdint>
#include <math.h>

// Reference model (survivor of 7 falsification rounds):
//   freqs_j = fl32(pi_f * expf_IEEE(fl32(j * ln2_f)))   [jax exp2 -> exp(x*ln2),
//             constant-folded host-side with IEEE-accurate expf]
//   ang_j   = fl32(x * freqs_j)
//   out     = accurate cos/sin of ang_j
// Freq table reconstructed mechanically in a setup kernel via DOUBLE exp
// (immune to --use_fast_math, which sabotaged round 10's float expf).
// sin/cos via exact 192-bit integer Payne-Hanek + cephes polys (validated).

__device__ float g_freqs[32];

__global__ void init_freqs_kernel() {
    int j = threadIdx.x;
    if (j < 32) {
        const float LN2_F = 0.693147180559945309417f;  // fl32 -> 0x3F317218
        const float PI_F  = 3.14159265358979323846f;   // fl32 -> 0x40490FDB
        float a = __fmul_rn((float)j, LN2_F);          // fl32(j * ln2_f)
        double e = exp((double)a);                     // IEEE-accurate, fast-math-proof
        g_freqs[j] = __fmul_rn(PI_F, (float)e);
    }
}

// 1/(2*pi) fraction bits 1..192
#define W0 0x28BE60DB9391054AULL
#define W1 0x7F09D5F47D4D3770ULL
#define W2 0x36D8A5664F10E410ULL

// frac(a / (2*pi)) * 2^64 for float a >= 0 (exact integer Payne-Hanek)
static __device__ __forceinline__ unsigned long long ph_frac64(float a) {
    unsigned int ia = __float_as_uint(a);
    int E = (int)((ia >> 23) & 0xFFu);
    unsigned long long M = (unsigned long long)((ia & 0x7FFFFFu) | 0x800000u);
    int t = E - 86;
    if (t < 0) return 0ULL;            // |angle| < ~2^-41
    unsigned long long A, B, C;
    if (t >= 64) { A = W0; B = W1; C = W2; t -= 64; }
    else         { A = 0ULL; B = W0; C = W1; }
    unsigned long long hi, lo;
    if (t == 0) { hi = A; lo = B; }
    else {
        hi = (A << t) | (B >> (64 - t));
        lo = (B << t) | (C >> (64 - t));
    }
    return M * hi + __umul64hi(M, lo); // middle 64 bits of M*(hi:lo) = frac * 2^64
}

// sin/cos of angle = 2*pi * (T / 2^64), ~1 ulp
static __device__ __forceinline__ void sincos_turn64(unsigned long long T,
                                                     float& s_out, float& c_out) {
    const float Kc = 3.4061215800865545e-19f;          // 2*pi / 2^64
    unsigned long long w = T + 0x2000000000000000ULL;  // + half quadrant (wraps)
    unsigned int q = (unsigned int)(w >> 62);          // quadrant 0..3
    long long z = (long long)(w & 0x3FFFFFFFFFFFFFFFULL) - 0x2000000000000000LL;
    float th = (float)z * Kc;                          // [-pi/4, pi/4)
    float t2 = th * th;

    float ps = fmaf(-1.9515295891e-4f, t2, 8.3321608736e-3f);
    ps = fmaf(ps, t2, -1.6666654611e-1f);
    float sp = fmaf(th * t2, ps, th);

    float pc = fmaf(2.443315711810e-5f, t2, -1.388731625493765e-3f);
    pc = fmaf(pc, t2, 4.166664568298827e-2f);
    float cp = fmaf(t2, fmaf(t2, pc, -0.5f), 1.0f);

    bool sw = (q & 1u) != 0u;
    float cv = sw ? sp : cp;
    float sv = sw ? cp : sp;
    if ((q + 1u) & 2u) cv = -cv;       // cos < 0 for q = 1, 2
    if (q & 2u) sv = -sv;              // sin < 0 for q = 2, 3
    c_out = cv;
    s_out = sv;
}

__global__ void __launch_bounds__(256)
encoder_kernel(const float* __restrict__ x, float4* __restrict__ out, int n) {
    long long gtid = (long long)blockIdx.x * blockDim.x + threadIdx.x;
    int e = (int)(gtid >> 4);   // element index
    int p = (int)(gtid & 15);   // j-pair: j0 = 2p, j1 = 2p+1
    if (e >= n) return;

    float xv = __ldg(&x[e]);

    int j0 = 2 * p, j1 = j0 + 1;
    float f0 = g_freqs[j0];            // reconstructed reference freq bits
    float f1 = g_freqs[j1];

    float ang0 = __fmul_rn(xv, f0);    // bit-identical to reference's angle
    float ang1 = __fmul_rn(xv, f1);

    float s0, c0, s1, c1;
    sincos_turn64(ph_frac64(ang0), s0, c0);
    sincos_turn64(ph_frac64(ang1), s1, c1);

    __stcs(&out[gtid], make_float4(c0, s0, c1, s1));
}

extern "C" void kernel_launch(void* const* d_in, const int* in_sizes, int n_in,
                              void* d_out, int out_size) {
    const float* x = (const float*)d_in[0];
    int n = in_sizes[0];
    init_freqs_kernel<<<1, 32>>>();     // stream-ordered before main kernel
    long long total = (long long)n * 16;
    int threads = 256;
    long long blocks = (total + threads - 1) / threads;
    encoder_kernel<<<(int)blocks, threads>>>(x, (float4*)d_out, n);
}

// round 12
// speedup vs baseline: 1.1951x; 1.1951x over previous
#include <cuda_runtime.h>
#include <cstdint>
#include <math.h>

// freqs_j = fl32(pi_f * exp_IEEE(fl32(j*ln2_f)))  (reconstructed in init kernel)
// ang_j   = fl32(x * freqs_j) = fl32(x * s_j) * 2^j,  s_j = freqs_j * 2^-j (exact)
// u = frac(ang/2pi)*2^64 via ONE integer Payne-Hanek per thread + exact linear
// mantissa correction per level; sincos on top-32 phase bits.

#define W0 0x28BE60DB9391054AULL   // 1/(2*pi) fraction bits 1..64
#define W1 0x7F09D5F47D4D3770ULL   // bits 65..128

__device__ float2 g_s2[16];        // s_{2p}, s_{2p+1}

__global__ void init_freqs_kernel() {
    int j = threadIdx.x;
    if (j < 32) {
        const float LN2_F = 0.693147180559945309417f;  // 0x3F317218
        const float PI_F  = 3.14159265358979323846f;   // 0x40490FDB
        float a = __fmul_rn((float)j, LN2_F);
        double ev = exp((double)a);                    // IEEE, fast-math-proof
        float fr = __fmul_rn(PI_F, (float)ev);         // reference freq bits
        ((float*)g_s2)[j] = ldexpf(fr, -j);            // exact scale to [pi, 2pi)
    }
}

// cos/sin of angle = 2*pi * (h / 2^32)
static __device__ __forceinline__ float2 cs_turn32(unsigned h) {
    const float Kc = 1.46291807926715968e-9f;          // 2*pi / 2^32
    unsigned w = h + 0x20000000u;                      // + half quadrant (wraps)
    unsigned q = w >> 30;
    int zi = (int)(w & 0x3FFFFFFFu) - 0x20000000;      // centered remainder
    float th = (float)zi * Kc;                         // [-pi/4, pi/4)
    float t2 = th * th;

    float ps = fmaf(-1.9515295891e-4f, t2, 8.3321608736e-3f);
    ps = fmaf(ps, t2, -1.6666654611e-1f);
    float sp = fmaf(th * t2, ps, th);

    float pc = fmaf(2.443315711810e-5f, t2, -1.388731625493765e-3f);
    pc = fmaf(pc, t2, 4.166664568298827e-2f);
    float cp = fmaf(t2, fmaf(t2, pc, -0.5f), 1.0f);

    bool sw = (q & 1u) != 0u;
    float cv = sw ? sp : cp;
    float sv = sw ? cp : sp;
    unsigned sgc = ((q + 1u) & 2u) << 30;              // cos < 0 for q = 1,2
    unsigned sgs = (q & 2u) << 30;                     // sin < 0 for q = 2,3
    cv = __uint_as_float(__float_as_uint(cv) ^ sgc);
    sv = __uint_as_float(__float_as_uint(sv) ^ sgs);
    return make_float2(cv, sv);
}

// One level: angle = fl32(x*s)*2^j. u_c = u0 + k*hi (exact linear correction).
static __device__ __forceinline__ float2 level_cs(
    float xv, float s, float y0, float invulp,
    unsigned long long u0, unsigned long long hi, int j)
{
    float yc = __fmul_rn(xv, s);
    float d  = __fsub_rn(yc, y0);             // exact (Sterbenz: yc/y0 ~ 1)
    int   k  = __float2int_rn(d * invulp);    // exact small integer (ulp count)
    unsigned long long u = u0 + (unsigned long long)((long long)k * (long long)hi);
    // h = top 32 bits of (u << j) = bits [32-j, 64-j) of u
    unsigned h = __funnelshift_rc((unsigned)u, (unsigned)(u >> 32), 32 - j);
    return cs_turn32(h);
}

__global__ void __launch_bounds__(256)
encoder_kernel(const float* __restrict__ x, float4* __restrict__ out, int n) {
    unsigned gtid = blockIdx.x * blockDim.x + threadIdx.x;   // < n*8 = 2^25
    unsigned e = gtid >> 3;          // element
    unsigned p = gtid & 7;           // handles j-pairs p and p+8
    if (e >= (unsigned)n) return;

    float xv = __ldg(&x[e]);

    // ---- one Payne-Hanek per thread on y0 = fl(x*pi_f) < pi ----
    float y0 = __fmul_rn(xv, 3.14159265358979323846f);
    unsigned iy = __float_as_uint(y0);
    int E = (int)((iy >> 23) & 0xFFu);       // E <= 128 -> t <= 42
    unsigned long long M = (unsigned long long)((iy & 0x7FFFFFu) | 0x800000u);
    int t = E - 86;
    unsigned long long hi = 0ULL, lo = 0ULL;
    if (t > 0) {
        hi = W0 >> (64 - t);
        lo = (W0 << t) | (W1 >> (64 - t));
    } else if (t == 0) {
        lo = W0;                              // x == 0 lands in t < 0 (u = 0)
    }
    unsigned long long u0 = M * hi + __umul64hi(M, lo);

    // invulp = 2^(150-E), exponent-field clamped (x==0 path yields k=0 anyway)
    int fld = 277 - E; if (fld > 254) fld = 254;
    float invulp = __uint_as_float((unsigned)fld << 23);

    // ---- 4 levels: j = 2p, 2p+1, 2p+16, 2p+17 ----
    float2 sA = g_s2[p];
    float2 sB = g_s2[p + 8];
    int jA = 2 * (int)p;
    int jB = jA + 16;

    float2 cs0 = level_cs(xv, sA.x, y0, invulp, u0, hi, jA);
    float2 cs1 = level_cs(xv, sA.y, y0, invulp, u0, hi, jA + 1);
    float2 cs2 = level_cs(xv, sB.x, y0, invulp, u0, hi, jB);
    float2 cs3 = level_cs(xv, sB.y, y0, invulp, u0, hi, jB + 1);

    // output float4 index: 16*e + p  and  16*e + p + 8  ( = 2*gtid - p )
    unsigned idx = 2u * gtid - p;
    __stcs(&out[idx],     make_float4(cs0.x, cs0.y, cs1.x, cs1.y));
    __stcs(&out[idx + 8], make_float4(cs2.x, cs2.y, cs3.x, cs3.y));
}

extern "C" void kernel_launch(void* const* d_in, const int* in_sizes, int n_in,
                              void* d_out, int out_size) {
    const float* x = (const float*)d_in[0];
    int n = in_sizes[0];
    init_freqs_kernel<<<1, 32>>>();
    long long total = (long long)n * 8;      // one thread per 2 output float4s
    int threads = 256;
    int blocks = (int)((total + threads - 1) / threads);
    encoder_kernel<<<blocks, threads>>>(x, (float4*)d_out, n);
}

// round 13
// speedup vs baseline: 1.7621x; 1.4745x over previous
#include <cuda_runtime.h>
#include <cstdint>
#include <math.h>

// freqs_j = fl32(pi_f * exp_IEEE(fl32(j*ln2_f)))  (reconstructed in init kernel)
// ang_j   = fl32(x * freqs_j) = fl32(x * s_j) * 2^j,  s_j = freqs_j * 2^-j (exact)
// Phase: ang_j = Mk_j * 2^(E0-150) * 2^j exactly, where Mk_j = M(y0) + k_j is the
// 25-bit corrected mantissa (k_j exact via Sterbenz subtract + exact scaling).
// u_j = frac(ang_j/2pi)*2^64 = Mk*hi + umul64hi(Mk, lo)  (window at y0's exponent,
// shared across all 4 levels; error <= 2 ulp of 2^-64 -> <= 2^-32 turn at j=31).

#define W0 0x28BE60DB9391054AULL   // 1/(2*pi) fraction bits 1..64
#define W1 0x7F09D5F47D4D3770ULL   // bits 65..128

__device__ float2 g_s2[16];        // (s_{2p}, s_{2p+1})

__global__ void init_freqs_kernel() {
    int j = threadIdx.x;
    if (j < 32) {
        const float LN2_F = 0.693147180559945309417f;  // 0x3F317218
        const float PI_F  = 3.14159265358979323846f;   // 0x40490FDB
        float a = __fmul_rn((float)j, LN2_F);
        double ev = exp((double)a);                    // IEEE, fast-math-proof
        float fr = __fmul_rn(PI_F, (float)ev);         // reference freq bits
        ((float*)g_s2)[j] = ldexpf(fr, -j);            // exact scale into [pi, 2pi)
    }
}

// cos/sin of angle = 2*pi * (h / 2^32)
static __device__ __forceinline__ float2 cs_turn32(unsigned h) {
    const float Kc = 1.46291807926715968e-9f;          // 2*pi / 2^32
    unsigned w = h + 0x20000000u;                      // + half quadrant (wraps)
    int zi = (int)(w & 0x3FFFFFFFu) - 0x20000000;      // centered remainder
    float th = (float)zi * Kc;                         // [-pi/4, pi/4)
    float t2 = th * th;

    float ps = fmaf(-1.9515295891e-4f, t2, 8.3321608736e-3f);
    ps = fmaf(ps, t2, -1.6666654611e-1f);
    float sp = fmaf(th * t2, ps, th);

    float pc = fmaf(2.443315711810e-5f, t2, -1.388731625493765e-3f);
    pc = fmaf(pc, t2, 4.166664568298827e-2f);
    float cp = fmaf(t2, fmaf(t2, pc, -0.5f), 1.0f);

    // quadrant from top bits of w: swap if bit30, signs from bit31 / bit31^bit30
    bool sw = (w & 0x40000000u) != 0u;
    float cv = sw ? sp : cp;
    float sv = sw ? cp : sp;
    unsigned sgs = w & 0x80000000u;                    // sin < 0 for q = 2,3
    unsigned sgc = (w ^ (w << 1)) & 0x80000000u;       // cos < 0 for q = 1,2
    cv = __uint_as_float(__float_as_uint(cv) ^ sgc);
    sv = __uint_as_float(__float_as_uint(sv) ^ sgs);
    return make_float2(cv, sv);
}

// One level: 32-bit corrected mantissa, full (hi:lo) product, single funnel shift.
static __device__ __forceinline__ float2 level_cs(
    float xv, float s, float y0, float invulp, unsigned M,
    unsigned long long hi, unsigned lo_hi, unsigned lo_lo, int j)
{
    float yc = __fmul_rn(xv, s);
    float d  = __fsub_rn(yc, y0);                 // exact (Sterbenz: yc in [y0, 2*y0])
    int   k  = __float2int_rn(__fmul_rn(d, invulp));   // exact ulp count
    unsigned Mk = M + (unsigned)k;                // 25-bit corrected mantissa
    // u = Mk*hi + floor(Mk*lo / 2^64), all with 32x32->64 wide mads
    unsigned long long a = (unsigned long long)Mk * lo_hi;
    unsigned long long b = (unsigned long long)Mk * lo_lo;
    unsigned long long u = (unsigned long long)Mk * hi + ((a + (b >> 32)) >> 32);
    // h = top 32 bits of (u << j)
    unsigned h = __funnelshift_rc((unsigned)u, (unsigned)(u >> 32), (unsigned)(32 - j));
    return cs_turn32(h);
}

__global__ void __launch_bounds__(256)
encoder_kernel(const float* __restrict__ x, float4* __restrict__ out, int n) {
    unsigned gtid = blockIdx.x * blockDim.x + threadIdx.x;   // < n*8 = 2^25
    unsigned e = gtid >> 3;          // element
    unsigned p = gtid & 7;           // handles j-pairs p and p+8
    if (e >= (unsigned)n) return;

    float xv = __ldg(&x[e]);

    // ---- one Payne-Hanek window per thread, at y0 = fl(x*pi_f) < pi ----
    float y0 = __fmul_rn(xv, 3.14159265358979323846f);
    unsigned iy = __float_as_uint(y0);
    int E = (int)(iy >> 23);                 // y0 >= 0
    unsigned M = (iy & 0x7FFFFFu) | 0x800000u;
    int t = E - 86;                          // window shift, t <= 42
    unsigned long long hi, lo;
    if (t > 0) {
        hi = W0 >> (64 - t);
        lo = (W0 << t) | (W1 >> (64 - t));
    } else {
        hi = 0ULL;
        lo = (t > -64) ? (W0 >> (-t)) : 0ULL;
    }
    unsigned lo_hi = (unsigned)(lo >> 32), lo_lo = (unsigned)lo;

    // invulp = 2^(150-E): exact scale from d to integer ulp count
    int fld = 277 - E; if (fld > 254) fld = 254;
    float invulp = __uint_as_float((unsigned)fld << 23);

    // ---- 4 levels: j = 2p, 2p+1, 2p+16, 2p+17 ----
    float2 sA = g_s2[p];
    float2 sB = g_s2[p + 8];
    int jA = 2 * (int)p;
    int jB = jA + 16;

    float2 cs0 = level_cs(xv, sA.x, y0, invulp, M, hi, lo_hi, lo_lo, jA);
    float2 cs1 = level_cs(xv, sA.y, y0, invulp, M, hi, lo_hi, lo_lo, jA + 1);
    float2 cs2 = level_cs(xv, sB.x, y0, invulp, M, hi, lo_hi, lo_lo, jB);
    float2 cs3 = level_cs(xv, sB.y, y0, invulp, M, hi, lo_hi, lo_lo, jB + 1);

    // output float4 index: 16*e + p and 16*e + p + 8  ( = 2*gtid - p )
    unsigned idx = 2u * gtid - p;
    __stcs(&out[idx],     make_float4(cs0.x, cs0.y, cs1.x, cs1.y));
    __stcs(&out[idx + 8], make_float4(cs2.x, cs2.y, cs3.x, cs3.y));
}

extern "C" void kernel_launch(void* const* d_in, const int* in_sizes, int n_in,
                              void* d_out, int out_size) {
    const float* x = (const float*)d_in[0];
    int n = in_sizes[0];
    init_freqs_kernel<<<1, 32>>>();
    long long total = (long long)n * 8;      // one thread per 2 output float4s
    int threads = 256;
    int blocks = (int)((total + threads - 1) / threads);
    encoder_kernel<<<blocks, threads>>>(x, (float4*)d_out, n);
}

// round 14
// speedup vs baseline: 2.0517x; 1.1644x over previous
#include <cuda_runtime.h>
#include <cstdint>
#include <math.h>

// freqs_j = fl32(pi_f * exp_IEEE(fl32(j*ln2_f)))  (reconstructed in init kernel)
// ang_j = fl32(x * freqs_j) = fl32(x * s_j) * 2^j,  s_j = freqs_j * 2^-j (exact)
// Anchor at exponent E-1 (M2 = 2*M, 25 bits) so every yc = fl(x*s_j) is an
// EXACT integer multiple Mk = M2 + k of the anchor ulp (fixes half-ulp
// binade-crossing bug that caused rel_err 2.8e-4 in R12/R13).
// Phase: u_j = U0 + k_j*hi (per-ulp phase step = hi + lo/2^64; k*lo dropped,
// <= 2^-26 turn after <<31).  h_j = top 32 bits of (u_j << j) -> 32-bit sincos.

#define W0 0x28BE60DB9391054AULL   // 1/(2*pi) fraction bits 1..64
#define W1 0x7F09D5F47D4D3770ULL   // bits 65..128

__device__ float2 g_s2[16];        // (s_{2p}, s_{2p+1})

__global__ void init_freqs_kernel() {
    int j = threadIdx.x;
    if (j < 32) {
        const float LN2_F = 0.693147180559945309417f;  // 0x3F317218
        const float PI_F  = 3.14159265358979323846f;   // 0x40490FDB
        float a = __fmul_rn((float)j, LN2_F);
        double ev = exp((double)a);                    // IEEE, fast-math-proof
        float fr = __fmul_rn(PI_F, (float)ev);         // reference freq bits
        ((float*)g_s2)[j] = ldexpf(fr, -j);            // exact: ~pi*(1 +- 2.5e-6)
    }
}

// cos/sin of angle = 2*pi * (h / 2^32)   (corner-verified)
static __device__ __forceinline__ float2 cs_turn32(unsigned h) {
    const float Kc = 1.46291807926715968e-9f;          // 2*pi / 2^32
    unsigned w = h + 0x20000000u;                      // + half quadrant (wraps)
    int zi = (int)(w & 0x3FFFFFFFu) - 0x20000000;      // centered remainder
    float th = (float)zi * Kc;                         // [-pi/4, pi/4)
    float t2 = th * th;

    float ps = fmaf(-1.9515295891e-4f, t2, 8.3321608736e-3f);
    ps = fmaf(ps, t2, -1.6666654611e-1f);
    float sp = fmaf(th * t2, ps, th);

    float pc = fmaf(2.443315711810e-5f, t2, -1.388731625493765e-3f);
    pc = fmaf(pc, t2, 4.166664568298827e-2f);
    float cp = fmaf(t2, fmaf(t2, pc, -0.5f), 1.0f);

    bool sw = (w & 0x40000000u) != 0u;                 // swap in odd quadrants
    float cv = sw ? sp : cp;
    float sv = sw ? cp : sp;
    unsigned sgs = w & 0x80000000u;                    // sin < 0 for q = 2,3
    unsigned sgc = (w ^ (w << 1)) & 0x80000000u;       // cos < 0 for q = 1,2
    cv = __uint_as_float(__float_as_uint(cv) ^ sgc);
    sv = __uint_as_float(__float_as_uint(sv) ^ sgs);
    return make_float2(cv, sv);
}

// One level: k = exact ulp offset of fl(x*s) from anchor; phase via U0 + k*hi.
static __device__ __forceinline__ float2 level_cs(
    float xv, float s, float y0, float invulp,
    unsigned long long U0, unsigned long long hi, int j)
{
    float yc = __fmul_rn(xv, s);
    float d  = __fsub_rn(yc, y0);                      // exact (Sterbenz)
    int   k  = __float2int_rn(__fmul_rn(d, invulp));   // exact: |k| <= ~84
    unsigned long long u = U0 + (unsigned long long)((long long)k) * hi;
    unsigned h = __funnelshift_rc((unsigned)u, (unsigned)(u >> 32),
                                  (unsigned)(32 - j));
    return cs_turn32(h);
}

__global__ void __launch_bounds__(256)
encoder_kernel(const float* __restrict__ x, float4* __restrict__ out, int n) {
    unsigned gtid = blockIdx.x * blockDim.x + threadIdx.x;   // < n*4 = 2^24
    unsigned e = gtid >> 2;          // element
    unsigned p = gtid & 3;           // owns float4 slots p, p+4, p+8, p+12
    if (e >= (unsigned)n) return;

    float xv = __ldg(&x[e]);

    // ---- anchor at exponent E-1: y0 = M2 * 2^(E-151), M2 = 2*M (25 bits) ----
    float y0 = __fmul_rn(xv, 3.14159265358979323846f);
    unsigned iy = __float_as_uint(y0);
    int E = (int)(iy >> 23);
    unsigned M2 = (((iy & 0x7FFFFFu) | 0x800000u) << 1);
    int t = E - 87;                          // window shift, t in [1, 41] normally
    unsigned long long hi = 0ULL, lo = 0ULL;
    if (t >= 1) {                            // y0 >= 2^-39; else phases ~0
        hi = W0 >> (64 - t);
        lo = (W0 << t) | (W1 >> (64 - t));
    }
    // U0 = M2*hi + floor(M2*lo / 2^64)
    unsigned long long a = (unsigned long long)M2 * (unsigned)(lo >> 32);
    unsigned long long b = (unsigned long long)M2 * (unsigned)lo;
    unsigned long long U0 = (unsigned long long)M2 * hi + ((a + (b >> 32)) >> 32);

    // invulp = 2^(151-E), exact d -> ulp-count scale (clamped for tiny E)
    int fld = 278 - E; if (fld > 254) fld = 254; if (fld < 1) fld = 1;
    float invulp = __uint_as_float((unsigned)fld << 23);

    // ---- 8 levels in 4 slot-pairs; store each float4 as soon as ready ----
    unsigned idx = 4u * gtid - 3u * p;       // = 16*e + p
    #pragma unroll
    for (int ss = 0; ss < 4; ss++) {
        int slot = (int)p + 4 * ss;          // j-pair index
        float2 sv = g_s2[slot];
        int j = 2 * slot;
        float2 c0 = level_cs(xv, sv.x, y0, invulp, U0, hi, j);
        float2 c1 = level_cs(xv, sv.y, y0, invulp, U0, hi, j + 1);
        __stcs(&out[idx + 4u * ss], make_float4(c0.x, c0.y, c1.x, c1.y));
    }
}

extern "C" void kernel_launch(void* const* d_in, const int* in_sizes, int n_in,
                              void* d_out, int out_size) {
    const float* x = (const float*)d_in[0];
    int n = in_sizes[0];
    init_freqs_kernel<<<1, 32>>>();
    long long total = (long long)n * 4;      // one thread per 4 output float4s
    int threads = 256;
    int blocks = (int)((total + threads - 1) / threads);
    encoder_kernel<<<blocks, threads>>>(x, (float4*)d_out, n);
}

// round 15
// speedup vs baseline: 2.8360x; 1.3823x over previous
#include <cuda_runtime.h>
#include <cstdint>
#include <math.h>

// freqs_j = fl32(pi_f * exp_IEEE(fl32(j*ln2_f)))  (reconstructed in init kernel)
// ang_j = fl32(x * freqs_j) = fl32(x * s_j) * 2^j,  s_j = freqs_j * 2^-j (exact)
// Anchor at exponent E-1 (M2 = 2M, 25 bits): every yc = fl(x*s_j) is an exact
// integer multiple M2 + k of the anchor ulp. Phase u_j = U0 + k_j*hi.
// k extracted via magic-FMA (exact); magic bias pre-folded into U0'.
// h_j = top32(u_j << j) = exact 32-bit turn fraction; theta = (int)h * 2pi/2^32
// in [-pi, pi); hardware RRO+MUFU (__sincosf) does quadrants + sin/cos
// (abs err 2^-21.4, 3000x inside the 1e-3 threshold).

#define W0 0x28BE60DB9391054AULL   // 1/(2*pi) fraction bits 1..64
#define W1 0x7F09D5F47D4D3770ULL   // bits 65..128

__device__ float2 g_s2[16];        // (s_{2p}, s_{2p+1})

__global__ void init_freqs_kernel() {
    int j = threadIdx.x;
    if (j < 32) {
        const float LN2_F = 0.693147180559945309417f;  // 0x3F317218
        const float PI_F  = 3.14159265358979323846f;   // 0x40490FDB
        float a = __fmul_rn((float)j, LN2_F);
        double ev = exp((double)a);                    // IEEE, fast-math-proof
        float fr = __fmul_rn(PI_F, (float)ev);         // reference freq bits
        ((float*)g_s2)[j] = ldexpf(fr, -j);            // exact: ~pi*(1 +- 2.5e-6)
    }
}

// One level: exact ulp offset via magic-FMA, phase via U0' + khat*hi,
// hardware sincos on the full-circle angle.
static __device__ __forceinline__ float2 level_cs(
    float xv, float s, float y0, float invulp,
    unsigned long long U0p, unsigned long long hi, int j)
{
    float yc = __fmul_rn(xv, s);
    float d  = __fsub_rn(yc, y0);                      // exact (Sterbenz)
    // khat = 0x4B400000 + k, exact for |k| < 2^22 (here |k| <= ~84)
    unsigned khat = __float_as_uint(__fmaf_rn(d, invulp, 12582912.0f));
    unsigned long long u = U0p + (unsigned long long)khat * hi;
    unsigned h = __funnelshift_rc((unsigned)u, (unsigned)(u >> 32),
                                  (unsigned)(32 - j));
    float th = (float)(int)h * 1.46291807926715968e-9f;  // 2pi/2^32 -> [-pi, pi)
    float sv, cv;
    __sincosf(th, &sv, &cv);                           // RRO + MUFU.SIN + MUFU.COS
    return make_float2(cv, sv);
}

__global__ void __launch_bounds__(256)
encoder_kernel(const float* __restrict__ x, float4* __restrict__ out, int n) {
    unsigned gtid = blockIdx.x * blockDim.x + threadIdx.x;   // < n*4 = 2^24
    unsigned e = gtid >> 2;          // element
    unsigned p = gtid & 3;           // owns float4 slots p, p+4, p+8, p+12
    if (e >= (unsigned)n) return;

    float xv = __ldg(&x[e]);

    // ---- anchor at exponent E-1: y0 = M2 * 2^(E-151), M2 = 2*M (25 bits) ----
    float y0 = __fmul_rn(xv, 3.14159265358979323846f);
    unsigned iy = __float_as_uint(y0);
    int E = (int)(iy >> 23);
    unsigned M2 = (((iy & 0x7FFFFFu) | 0x800000u) << 1);
    int t = E - 87;                          // window shift, t in [1, 41] normally
    unsigned long long hi = 0ULL, lo = 0ULL;
    if (t >= 1) {                            // else x == 0 -> all phases 0
        hi = W0 >> (64 - t);
        lo = (W0 << t) | (W1 >> (64 - t));
    }
    // U0 = M2*hi + floor(M2*lo / 2^64), then fold out the magic bias
    unsigned long long a = (unsigned long long)M2 * (unsigned)(lo >> 32);
    unsigned long long b = (unsigned long long)M2 * (unsigned)lo;
    unsigned long long U0 = (unsigned long long)M2 * hi + ((a + (b >> 32)) >> 32);
    unsigned long long U0p = U0 - 0x4B400000ULL * hi;   // u = U0p + khat*hi

    // invulp = 2^(151-E): exact d -> ulp-count scale (clamped for tiny E)
    int fld = 278 - E; if (fld > 254) fld = 254; if (fld < 1) fld = 1;
    float invulp = __uint_as_float((unsigned)fld << 23);

    // ---- 8 levels in 4 slot-pairs; store each float4 as soon as ready ----
    unsigned idx = 4u * gtid - 3u * p;       // = 16*e + p
    #pragma unroll
    for (int ss = 0; ss < 4; ss++) {
        int slot = (int)p + 4 * ss;          // j-pair index
        float2 sv = g_s2[slot];
        int j = 2 * slot;
        float2 c0 = level_cs(xv, sv.x, y0, invulp, U0p, hi, j);
        float2 c1 = level_cs(xv, sv.y, y0, invulp, U0p, hi, j + 1);
        __stcs(&out[idx + 4u * ss], make_float4(c0.x, c0.y, c1.x, c1.y));
    }
}

extern "C" void kernel_launch(void* const* d_in, const int* in_sizes, int n_in,
                              void* d_out, int out_size) {
    const float* x = (const float*)d_in[0];
    int n = in_sizes[0];
    init_freqs_kernel<<<1, 32>>>();
    long long total = (long long)n * 4;      // one thread per 4 output float4s
    int threads = 256;
    int blocks = (int)((total + threads - 1) / threads);
    encoder_kernel<<<blocks, threads>>>(x, (float4*)d_out, n);
}